// round 1
// baseline (speedup 1.0000x reference)
#include <cuda_runtime.h>
#include <cuda_bf16.h>
#include <math.h>

#define Nn 16
#define Cc 64
#define Tt 300
#define Vv 25
#define NHh 4
#define DKH 16
#define Bb (Nn*Vv)          // 400
#define QKVO 192            // 2*DK+DV

// Scratch (static device memory; no runtime allocation)
__device__ float g_qkv[(size_t)Bb * QKVO * Tt];    // 23,040,000 floats
__device__ float g_attn[(size_t)Bb * 64 * Tt];     //  7,680,000 floats

// ---------------------------------------------------------------------------
// Kernel 1: fused data_bn (eval) + 1x1 qkv conv. One block per b = n*25+v.
// smem: xs[64*300] normalized input, Wt[c][o] transposed weights, sc/bi per c.
// ---------------------------------------------------------------------------
__global__ void __launch_bounds__(256) qkv_kernel(
    const float* __restrict__ x,
    const float* __restrict__ dg, const float* __restrict__ db,
    const float* __restrict__ dm, const float* __restrict__ dv,
    const float* __restrict__ W,  const float* __restrict__ Wb)
{
    int b = blockIdx.x;
    int n = b / Vv, v = b - n * Vv;
    extern __shared__ float sm[];
    float* xs = sm;             // 19200
    float* Wt = xs + 19200;     // 12288  Wt[c*192+o] = W[o*64+c]
    float* sc = Wt + 12288;     // 64
    float* bi = sc + 64;        // 64
    int tid = threadIdx.x;

    if (tid < 64) {
        int idx = tid * Vv + v;
        float s = dg[idx] * rsqrtf(dv[idx] + 1e-5f);
        sc[tid] = s;
        bi[tid] = db[idx] - dm[idx] * s;
    }
    for (int i = tid; i < 192 * 64; i += 256) {
        int c = i / 192, o = i - c * 192;
        Wt[i] = W[o * 64 + c];
    }
    __syncthreads();

    const float* xb = x + ((size_t)n * Cc) * Tt * Vv + v;
    for (int i = tid; i < 64 * Tt; i += 256) {
        int c = i / Tt, t = i - c * Tt;
        xs[i] = xb[(size_t)(c * Tt + t) * Vv] * sc[c] + bi[c];
    }
    __syncthreads();

    // 192x300 outputs in 4x4 tiles: 48*75 = 3600 tiles
    for (int tile = tid; tile < 3600; tile += 256) {
        int og = tile / 75, tg = tile - og * 75;
        int o0 = og * 4, t0 = tg * 4;
        float acc[4][4] = {};
        #pragma unroll 8
        for (int c = 0; c < 64; ++c) {
            float4 w4 = *(const float4*)(Wt + c * 192 + o0);
            float4 x4 = *(const float4*)(xs + c * Tt + t0);
            float wa[4] = {w4.x, w4.y, w4.z, w4.w};
            float xa[4] = {x4.x, x4.y, x4.z, x4.w};
            #pragma unroll
            for (int i = 0; i < 4; ++i)
                #pragma unroll
                for (int j = 0; j < 4; ++j)
                    acc[i][j] += wa[i] * xa[j];
        }
        float* outp = g_qkv + ((size_t)b * QKVO + o0) * Tt + t0;
        #pragma unroll
        for (int i = 0; i < 4; ++i) {
            float bias = Wb[o0 + i];
            float scale = (o0 + i < 64) ? 0.25f : 1.0f;  // q * DKH^-0.5
            float4 r;
            r.x = (acc[i][0] + bias) * scale;
            r.y = (acc[i][1] + bias) * scale;
            r.z = (acc[i][2] + bias) * scale;
            r.w = (acc[i][3] + bias) * scale;
            *(float4*)(outp + i * Tt) = r;
        }
    }
}

// ---------------------------------------------------------------------------
// Kernel 2: attention per (b,h). logits[t,s] = sum_d q[d,t]*(k[d,s]+kr[d,s-t+299])
// warp-per-row, registers hold the 300-wide probability row across 32 lanes.
// ---------------------------------------------------------------------------
__global__ void __launch_bounds__(256) attn_kernel(const float* __restrict__ key_rel)
{
    int bh = blockIdx.x;
    int b = bh >> 2, h = bh & 3;
    extern __shared__ float sm[];
    float* qs  = sm;            // 16*300
    float* ks  = qs + 4800;     // 16*300
    float* vs  = ks + 4800;     // 16*300
    float* krs = vs + 4800;     // 16*608 (transposed key_rel, padded rows)

    const float* base = g_qkv + (size_t)b * QKVO * Tt;
    const float* qg = base + (h * 16) * Tt;
    const float* kg = base + (64 + h * 16) * Tt;
    const float* vg = base + (128 + h * 16) * Tt;

    int tid = threadIdx.x;
    for (int i = tid; i < 4800; i += 256) { qs[i] = qg[i]; ks[i] = kg[i]; vs[i] = vg[i]; }
    for (int i = tid; i < 599 * 16; i += 256) {
        int m = i >> 4, d = i & 15;
        krs[d * 608 + m] = key_rel[i];
    }
    __syncthreads();

    int warp = tid >> 5, lane = tid & 31;
    for (int t = warp; t < Tt; t += 8) {
        float q[16];
        #pragma unroll
        for (int d = 0; d < 16; ++d) q[d] = qs[d * Tt + t];

        float w[10];
        float mx = -1e30f;
        #pragma unroll
        for (int j = 0; j < 10; ++j) {
            int s = j * 32 + lane;
            float acc = -1e30f;
            if (s < Tt) {
                int m = s - t + (Tt - 1);
                acc = 0.f;
                #pragma unroll
                for (int d = 0; d < 16; ++d)
                    acc += q[d] * (ks[d * Tt + s] + krs[d * 608 + m]);
            }
            w[j] = acc;
            mx = fmaxf(mx, acc);
        }
        #pragma unroll
        for (int o = 16; o > 0; o >>= 1) mx = fmaxf(mx, __shfl_xor_sync(0xffffffffu, mx, o));

        float sum = 0.f;
        #pragma unroll
        for (int j = 0; j < 10; ++j) {
            int s = j * 32 + lane;
            float e = (s < Tt) ? __expf(w[j] - mx) : 0.f;
            w[j] = e;
            sum += e;
        }
        #pragma unroll
        for (int o = 16; o > 0; o >>= 1) sum += __shfl_xor_sync(0xffffffffu, sum, o);
        float inv = 1.f / sum;
        #pragma unroll
        for (int j = 0; j < 10; ++j) w[j] *= inv;

        float* outp = g_attn + ((size_t)b * 64 + h * 16) * Tt + t;
        #pragma unroll
        for (int d = 0; d < 16; ++d) {
            float o = 0.f;
            #pragma unroll
            for (int j = 0; j < 10; ++j) {
                int s = j * 32 + lane;
                int scl = (s < Tt) ? s : (Tt - 1);   // w[j]==0 when invalid
                o += w[j] * vs[d * Tt + scl];
            }
            #pragma unroll
            for (int k = 16; k > 0; k >>= 1) o += __shfl_xor_sync(0xffffffffu, o, k);
            if (lane == 0) outp[d * Tt] = o;
        }
    }
}

// ---------------------------------------------------------------------------
// Kernel 3: head-mix projection + skip + BN + ReLU. One block per b.
// ---------------------------------------------------------------------------
__global__ void __launch_bounds__(256) proj_kernel(
    const float* __restrict__ Wa, const float* __restrict__ Ba,
    const float* __restrict__ bg, const float* __restrict__ bb,
    const float* __restrict__ bm, const float* __restrict__ bv,
    const float* __restrict__ x, float* __restrict__ out)
{
    int b = blockIdx.x;
    int n = b / Vv, v = b - n * Vv;
    extern __shared__ float sm[];
    float* as = sm;            // 64*300
    float* Wt = as + 19200;    // 64*64   Wt[d*64+o] = Wa[o*64+d]
    float* s2 = Wt + 4096;     // 64
    float* b2 = s2 + 64;       // 64
    int tid = threadIdx.x;

    const float* ag = g_attn + (size_t)b * 64 * Tt;
    for (int i = tid; i < 64 * Tt; i += 256) as[i] = ag[i];
    for (int i = tid; i < 4096; i += 256) {
        int d = i >> 6, o = i & 63;
        Wt[i] = Wa[o * 64 + d];
    }
    if (tid < 64) {
        float s = bg[tid] * rsqrtf(bv[tid] + 1e-5f);
        s2[tid] = s;
        b2[tid] = bb[tid] - bm[tid] * s;
    }
    __syncthreads();

    const float* xb = x + ((size_t)n * Cc) * Tt * Vv + v;
    float*       ob = out + ((size_t)n * Cc) * Tt * Vv + v;

    // 64x300 outputs in 4x4 tiles: 16*75 = 1200 tiles
    for (int tile = tid; tile < 1200; tile += 256) {
        int og = tile / 75, tg = tile - og * 75;
        int o0 = og * 4, t0 = tg * 4;
        float acc[4][4] = {};
        #pragma unroll 8
        for (int d = 0; d < 64; ++d) {
            float4 w4 = *(const float4*)(Wt + d * 64 + o0);
            float4 a4 = *(const float4*)(as + d * Tt + t0);
            float wa[4] = {w4.x, w4.y, w4.z, w4.w};
            float aa[4] = {a4.x, a4.y, a4.z, a4.w};
            #pragma unroll
            for (int i = 0; i < 4; ++i)
                #pragma unroll
                for (int j = 0; j < 4; ++j)
                    acc[i][j] += wa[i] * aa[j];
        }
        #pragma unroll
        for (int i = 0; i < 4; ++i) {
            int o = o0 + i;
            float bias = Ba[o];
            #pragma unroll
            for (int j = 0; j < 4; ++j) {
                int t = t0 + j;
                size_t gi = (size_t)(o * Tt + t) * Vv;
                float r = acc[i][j] + bias + xb[gi];
                r = r * s2[o] + b2[o];
                ob[gi] = fmaxf(r, 0.f);
            }
        }
    }
}

// ---------------------------------------------------------------------------
extern "C" void kernel_launch(void* const* d_in, const int* in_sizes, int n_in,
                              void* d_out, int out_size)
{
    const float* x       = (const float*)d_in[0];
    const float* dbn_g   = (const float*)d_in[1];
    const float* dbn_b   = (const float*)d_in[2];
    const float* dbn_m   = (const float*)d_in[3];
    const float* dbn_v   = (const float*)d_in[4];
    const float* qkv_w   = (const float*)d_in[5];
    const float* qkv_b   = (const float*)d_in[6];
    const float* key_rel = (const float*)d_in[7];
    const float* attn_w  = (const float*)d_in[8];
    const float* attn_b  = (const float*)d_in[9];
    const float* bn_g    = (const float*)d_in[10];
    const float* bn_b    = (const float*)d_in[11];
    const float* bn_m    = (const float*)d_in[12];
    const float* bn_v    = (const float*)d_in[13];
    float* out = (float*)d_out;

    const int SM1 = (19200 + 12288 + 128) * 4;          // 126464
    const int SM2 = (3 * 4800 + 16 * 608) * 4;          //  96512
    const int SM3 = (19200 + 4096 + 128) * 4;           //  93696

    cudaFuncSetAttribute(qkv_kernel,  cudaFuncAttributeMaxDynamicSharedMemorySize, SM1);
    cudaFuncSetAttribute(attn_kernel, cudaFuncAttributeMaxDynamicSharedMemorySize, SM2);
    cudaFuncSetAttribute(proj_kernel, cudaFuncAttributeMaxDynamicSharedMemorySize, SM3);

    qkv_kernel<<<Bb, 256, SM1>>>(x, dbn_g, dbn_b, dbn_m, dbn_v, qkv_w, qkv_b);
    attn_kernel<<<Bb * NHh, 256, SM2>>>(key_rel);
    proj_kernel<<<Bb, 256, SM3>>>(attn_w, attn_b, bn_g, bn_b, bn_m, bn_v, x, out);
}